// round 11
// baseline (speedup 1.0000x reference)
#include <cuda_runtime.h>
#include <cuda_fp16.h>
#include <math.h>

#ifndef M_PI
#define M_PI 3.14159265358979323846
#endif

// FOUR z-slices per sample via TWO half2 tiles (4-byte elements!):
//   tileA[r][c] = half2(z0,z1), tileB[r][c] = half2(z2,z3), each 76 x 263.
// TS=263 4-byte stride is the round-6-verified conflict-clean layout; using
// two 4B tiles (not one 8B tile) keeps the bank pattern identical to the
// 288us round-8 kernel while amortizing coordinate math over 4 samples.
// 4 y-band phases per slice-quad (verified round 5/10):
//   tile rows: 0,1 zero | 2..73 = 72 vol rows (64p-4 .. 64p+67, clamped) |
//   74,75 zero.  cols: 0,1 zero | 2..257 data | 258..262 zero/pad.
//   trow = floor(iy) - (64p-6), clamp [0,74]; tcol = floor(ix)+2, clamp [0,259].
#define TS    263
#define TROWS 76
#define TOFF  (TROWS * TS)            // uint offset of tileB
#define TILE_BYTES (2 * TROWS * TS * 4)

typedef unsigned long long ull;
typedef unsigned int uint;

#define FMA2(d,a,b,c) asm("fma.rn.f32x2 %0, %1, %2, %3;" : "=l"(d) : "l"(a), "l"(b), "l"(c))
#define ADD2(d,a,b)   asm("add.rn.f32x2 %0, %1, %2;"     : "=l"(d) : "l"(a), "l"(b))
#define PK2(d,lo,hi)  asm("mov.b64 %0, {%1, %2};"        : "=l"(d) : "f"(lo), "f"(hi))
#define UNPK2(lo,hi,v) asm("mov.b64 {%0, %1}, %2;"       : "=f"(lo), "=f"(hi) : "l"(v))
// fp16x2. PTX cvt.rn.f16x2.f32 d, a, b : a -> HIGH half, b -> LOW half.
#define HSUB2(d,a,b)   asm("sub.rn.f16x2 %0, %1, %2;"     : "=r"(d) : "r"(a), "r"(b))
#define HFMA2(d,a,b,c) asm("fma.rn.f16x2 %0, %1, %2, %3;" : "=r"(d) : "r"(a), "r"(b), "r"(c))
#define BCASTH(d,f)    asm("cvt.rn.f16x2.f32 %0, %1, %2;" : "=r"(d) : "f"(f), "f"(f))
#define PACKH(d,lo,hi) asm("cvt.rn.f16x2.f32 %0, %1, %2;" : "=r"(d) : "f"(hi), "f"(lo))
// half2 -> packed f32x2 (ull)
#define H2P2(d,v)      asm("{.reg .b16 l,h; .reg .f32 fl,fh; mov.b32 {l,h}, %1; " \
                           "cvt.f32.f16 fl, l; cvt.f32.f16 fh, h; mov.b64 %0, {fl, fh};}" \
                           : "=l"(d) : "r"(v))

__device__ int2 g_seg[4 * 4096];   // per (phase, view<<8|y): {xbeg, xend}

__global__ void fp_zero_kernel(float4* __restrict__ out, int n4) {
    int i = blockIdx.x * blockDim.x + threadIdx.x;
    if (i < n4) out[i] = make_float4(0.f, 0.f, 0.f, 0.f);
}

// z-independent line geometry, computed once.
__global__ void fp_range_kernel() {
    int i = blockIdx.x * 256 + threadIdx.x;   // (v<<8)|y
    int v = i >> 8, y = i & 255;
    float unit = (float)(M_PI / 16.0);
    float mu   = (float)(M_PI / 180.0);
    float a = __fadd_rn(mu, __fmul_rn((float)v, unit));
    double da = (double)a;
    float c = (float)cos(da), s = (float)sin(da);   // s > 0 for all views
    float yf = (float)y - 127.5f;
    float A = fmaf(-s, yf, fmaf(-c, 127.5f, 127.5f));  // ix = c*x + A
    float B = fmaf( c, yf, fmaf(-s, 127.5f, 127.5f));  // iy = s*x + B
    float inv_s = __fdividef(1.f, s);
    float inv_c = __fdividef(1.f, c);
    float xa = (-1.f  - B) * inv_s;
    float xb = (256.f - B) * inv_s;
    float e0 = (-2.f  - A) * inv_c;
    float e1 = (258.f - A) * inv_c;
    float lo = fmaxf(xa, fminf(e0, e1));
    float hi = fminf(xb, fmaxf(e0, e1));
    int xlo = max(0,   (int)floorf(lo) - 2);
    int xhi = min(256, (int)ceilf(hi) + 3);
    if (xhi < xlo) xhi = xlo;

    int xs[5];
    xs[0] = xlo; xs[4] = xhi;
    int prev = xlo;
    for (int k = 1; k <= 3; k++) {
        float b = 64.f * (float)k - 0.5f;
        int t = (int)floorf((b - B) * inv_s) + 1;  // iy(t) >= b (±1 slack)
        t = min(max(t, prev), xhi);
        xs[k] = t; prev = t;
    }
    for (int p = 0; p < 4; p++)
        g_seg[p * 4096 + i] = make_int2(xs[p], xs[p + 1]);
}

extern __shared__ uint tile[];   // [TOFF] = tileA (z0,z1), [TOFF..) = tileB (z2,z3)

__global__ void __launch_bounds__(1024, 1)
fp_main_kernel(const float* __restrict__ vol, float* __restrict__ out)
{
    const int bx  = blockIdx.x;
    const int zq  = bx >> 4;          // z-quad 0..63
    const int p   = (bx >> 2) & 3;    // y-band phase
    const int vg  = bx & 3;           // view group of 4
    const int tid = threadIdx.x;

    __shared__ float s_c[16], s_s[16], s_Ac[16], s_Bc[16];
    if (tid < 16) {
        float unit = (float)(M_PI / 16.0);
        float mu   = (float)(M_PI / 180.0);
        float a = __fadd_rn(mu, __fmul_rn((float)tid, unit));
        double da = (double)a;
        float c = (float)cos(da), s = (float)sin(da);
        s_c[tid] = c; s_s[tid] = s;
        s_Ac[tid] = fmaf(-c, 127.5f, 127.5f);
        s_Bc[tid] = fmaf(-s, 127.5f, 127.5f);
    }

    // zero both tiles, then overlay data rows
    for (int i = tid; i < 2 * TOFF; i += 1024) tile[i] = 0u;
    __syncthreads();

    const int vstart = 64 * p - 4;
    const int r0 = max(0, vstart);
    const int r1 = min(255, vstart + 71);
    const int nrows = r1 - r0 + 1;
    const int rowoff = r0 - vstart + 2;            // tile row of vol row r0
    const float* __restrict__ v0 = vol + ((size_t)(zq << 2) << 16) + (r0 << 8);
    const float* __restrict__ v1 = v0 + 65536;
    const float* __restrict__ v2 = v0 + 2 * 65536;
    const float* __restrict__ v3 = v0 + 3 * 65536;
    for (int i = tid; i < nrows * 64; i += 1024) {
        int r = i >> 6, c4 = (i & 63) << 2;
        int off = (r << 8) + c4;
        float4 a = *(const float4*)(v0 + off);
        float4 b = *(const float4*)(v1 + off);
        float4 c = *(const float4*)(v2 + off);
        float4 d = *(const float4*)(v3 + off);
        uint* dA = &tile[(r + rowoff) * TS + 2 + c4];
        uint* dB = dA + TOFF;
        uint t;
        PACKH(t, a.x, b.x); dA[0] = t;  PACKH(t, c.x, d.x); dB[0] = t;
        PACKH(t, a.y, b.y); dA[1] = t;  PACKH(t, c.y, d.y); dB[1] = t;
        PACKH(t, a.z, b.z); dA[2] = t;  PACKH(t, c.z, d.z); dB[2] = t;
        PACKH(t, a.w, b.w); dA[3] = t;  PACKH(t, c.w, d.w); dB[3] = t;
    }
    __syncthreads();

    const int warp = tid >> 5, lane = tid & 31;

    // magic-float bit-domain clamps: tcol in [0,259], trow in [0,74]
    const int      LO_MIN = 0x4B400000 - 2,          LO_MAX = LO_MIN + 259;
    const int      HI_MIN = 0x4B400000 + 64 * p - 6, HI_MAX = HI_MIN + 74;
    const unsigned UOFF   = (unsigned)HI_MIN * (unsigned)TS + (unsigned)LO_MIN;

    const ull MAGIC2  = 0x4B4000004B400000ULL;
    const ull NMAGIC2 = 0xCB400000CB400000ULL;
    const ull HALF2C  = 0x3F0000003F000000ULL;
    const ull NONE2   = 0xBF800000BF800000ULL;
    const ull STEP2   = 0x4200000042000000ULL;  // (32, 32)

    const int2* __restrict__ segp = &g_seg[p * 4096];

    for (int v4 = 0; v4 < 4; v4++) {
        const int v = (vg << 2) + v4;
        const float c = s_c[v], s = s_s[v], Ac = s_Ac[v], Bc = s_Bc[v];
        ull cs2; PK2(cs2, c, s);
        const int vi = v << 8;

        for (int y = warp; y < 256; y += 32) {
            int2 seg = __ldg(&segp[vi + y]);
            const int xbeg = seg.x, xend = seg.y;
            if (xbeg >= xend) continue;

            const float yf = (float)y - 127.5f;
            const float A = fmaf(-s, yf, Ac) - 0.5f;
            const float B = fmaf( c, yf, Bc) - 0.5f;
            ull ab2, xf2;
            PK2(ab2, A, B);
            const float xf0 = (float)(xbeg + lane);
            PK2(xf2, xf0, xf0);
            const int nb = (xend - xbeg + 31) >> 5;
            const float xcut = (float)xend;
            ull accP0 = 0ULL, accP1 = 0ULL;   // (z0,z1) and (z2,z3) fp32 sums

#define FP_BODY(TAILMASK)                                                     \
            {                                                                 \
                ull ih2, m2, f2, wh2, w2;                                     \
                FMA2(ih2, cs2, xf2, ab2);      /* (ix-.5, iy-.5) */           \
                ADD2(m2,  ih2, MAGIC2);                                       \
                ADD2(f2,  m2,  NMAGIC2);       /* (floor ix, floor iy) */     \
                FMA2(wh2, f2,  NONE2, ih2);                                   \
                ADD2(w2,  wh2, HALF2C);        /* (wx, wy) in [0,1] */        \
                int blo = (int)(unsigned)m2;                                  \
                int bhi = (int)(unsigned)(m2 >> 32);                          \
                blo = min(max(blo, LO_MIN), LO_MAX);                          \
                bhi = min(max(bhi, HI_MIN), HI_MAX);                          \
                unsigned idx = (unsigned)bhi * (unsigned)TS                   \
                             + (unsigned)blo - UOFF;                          \
                const uint* tA = &tile[idx];                                  \
                const uint* tB = tA + TOFF;                                   \
                uint A00 = tA[0], A01 = tA[1], A10 = tA[TS], A11 = tA[TS+1];  \
                uint B00 = tB[0], B01 = tB[1], B10 = tB[TS], B11 = tB[TS+1];  \
                float wx = __uint_as_float((unsigned)w2);                     \
                float wy = __uint_as_float((unsigned)(w2 >> 32));             \
                uint WX, WY; BCASTH(WX, wx); BCASTH(WY, wy);                  \
                uint D0, D1, H0, H1, DH, VALa, VALb;                          \
                HSUB2(D0, A01, A00);                                          \
                HSUB2(D1, A11, A10);                                          \
                HFMA2(H0, WX, D0, A00);                                       \
                HFMA2(H1, WX, D1, A10);                                       \
                HSUB2(DH, H1, H0);                                            \
                HFMA2(VALa, WY, DH, H0);                                      \
                HSUB2(D0, B01, B00);                                          \
                HSUB2(D1, B11, B10);                                          \
                HFMA2(H0, WX, D0, B00);                                       \
                HFMA2(H1, WX, D1, B10);                                       \
                HSUB2(DH, H1, H0);                                            \
                HFMA2(VALb, WY, DH, H0);                                      \
                TAILMASK                                                      \
                ull pa, pb;                                                   \
                H2P2(pa, VALa); H2P2(pb, VALb);                               \
                ADD2(accP0, accP0, pa);                                       \
                ADD2(accP1, accP1, pb);                                       \
                ADD2(xf2, xf2, STEP2);                                        \
            }

            for (int b = 0; b < nb - 1; b++) FP_BODY()
            FP_BODY(bool okx = __uint_as_float((unsigned)xf2) < xcut;
                    VALa = okx ? VALa : 0u; VALb = okx ? VALb : 0u;)
#undef FP_BODY

            #pragma unroll
            for (int o = 16; o; o >>= 1) {
                ull t0 = __shfl_xor_sync(0xffffffffu, accP0, o);
                ull t1 = __shfl_xor_sync(0xffffffffu, accP1, o);
                ADD2(accP0, accP0, t0);
                ADD2(accP1, accP1, t1);
            }
            if (lane == 0) {
                int oidx = ((((zq << 2) << 8) + y) << 4) + v;
                float a0, a1, a2, a3;
                UNPK2(a0, a1, accP0);
                UNPK2(a2, a3, accP1);
                atomicAdd(&out[oidx],            a0);
                atomicAdd(&out[oidx +     4096], a1);
                atomicAdd(&out[oidx + 2 * 4096], a2);
                atomicAdd(&out[oidx + 3 * 4096], a3);
            }
        }
    }
}

extern "C" void kernel_launch(void* const* d_in, const int* in_sizes, int n_in,
                              void* d_out, int out_size) {
    (void)in_sizes; (void)n_in;
    cudaFuncSetAttribute(fp_main_kernel,
                         cudaFuncAttributeMaxDynamicSharedMemorySize, TILE_BYTES);
    fp_zero_kernel<<<512, 512>>>((float4*)d_out, out_size / 4);
    fp_range_kernel<<<16, 256>>>();
    fp_main_kernel<<<1024, 1024, TILE_BYTES>>>((const float*)d_in[0], (float*)d_out);
}

// round 13
// speedup vs baseline: 1.1116x; 1.1116x over previous
#include <cuda_runtime.h>
#include <cuda_fp16.h>
#include <math.h>

#ifndef M_PI
#define M_PI 3.14159265358979323846
#endif

// z-pair half2 tile (lo=z0, hi=z1), TS=263 conflict-clean stride.
// LANE = Y-LINE layout: warp = (view, 32 consecutive y); x is a uniform
// scalar loop over the warp's union range; validity via clamp-to-zero guards
// + one seam-kill predicate keyed on floor(iy) ownership:
//   p0 owns floor(iy) <= 127 (trow 0..129), p1 owns floor(iy) >= 128 (trow 5..133).
// Ranges derive from the iy=128.0 crossing t128 (consistent with ownership):
//   p0: [xlo, min(xhi, t128+3)) ; p1: [max(xlo, t128-2), xhi) — overlap is
//   computed in both phases, kill predicate single-counts.
//   tile rows: p0 vol rows 0..128 at trows 2..130; p1 vol rows 128..255 at
//   trows 5..132; rows 0,1 and 133,134 (and unused) zero.
//   cols: 0,1 zero | 2..257 data | 258..262 zero/pad
#define TS    263
#define TROWS 135
#define TILE_BYTES (TROWS * TS * 4)

typedef unsigned long long ull;
typedef unsigned int uint;

#define FMA2(d,a,b,c) asm("fma.rn.f32x2 %0, %1, %2, %3;" : "=l"(d) : "l"(a), "l"(b), "l"(c))
#define ADD2(d,a,b)   asm("add.rn.f32x2 %0, %1, %2;"     : "=l"(d) : "l"(a), "l"(b))
#define PK2(d,lo,hi)  asm("mov.b64 %0, {%1, %2};"        : "=l"(d) : "f"(lo), "f"(hi))
#define UNPK2(lo,hi,v) asm("mov.b64 {%0, %1}, %2;"       : "=f"(lo), "=f"(hi) : "l"(v))
// fp16x2. PTX cvt.rn.f16x2.f32 d, a, b : a -> HIGH half, b -> LOW half.
#define HSUB2(d,a,b)   asm("sub.rn.f16x2 %0, %1, %2;"     : "=r"(d) : "r"(a), "r"(b))
#define HFMA2(d,a,b,c) asm("fma.rn.f16x2 %0, %1, %2, %3;" : "=r"(d) : "r"(a), "r"(b), "r"(c))
#define BCASTH(d,f)    asm("cvt.rn.f16x2.f32 %0, %1, %2;" : "=r"(d) : "f"(f), "f"(f))
#define PACKH(d,lo,hi) asm("cvt.rn.f16x2.f32 %0, %1, %2;" : "=r"(d) : "f"(hi), "f"(lo))
// half2 -> packed f32x2 (ull)
#define H2P2(d,v)      asm("{.reg .b16 l,h; .reg .f32 fl,fh; mov.b32 {l,h}, %1; " \
                           "cvt.f32.f16 fl, l; cvt.f32.f16 fh, h; mov.b64 %0, {fl, fh};}" \
                           : "=l"(d) : "r"(v))

__device__ int2 g_xrng[256];   // [p*128 + v*8 + yblk] = {xmin, xmax} union over 32 y

__global__ void fp_zero_kernel(float4* __restrict__ out, int n4) {
    int i = blockIdx.x * blockDim.x + threadIdx.x;
    if (i < n4) out[i] = make_float4(0.f, 0.f, 0.f, 0.f);
}

// Per (phase, view, y-block of 32): union of per-line active x ranges.
__global__ void fp_range_kernel() {
    int t = threadIdx.x;              // 0..255
    int p = t >> 7, v = (t >> 3) & 15, blk = t & 7;
    float unit = (float)(M_PI / 16.0);
    float mu   = (float)(M_PI / 180.0);
    float a = __fadd_rn(mu, __fmul_rn((float)v, unit));
    double da = (double)a;
    float c = (float)cos(da), s = (float)sin(da);   // s > 0 all views
    float inv_s = __fdividef(1.f, s);
    float inv_c = __fdividef(1.f, c);
    int mn = 256, mx = 0;
    for (int k = 0; k < 32; k++) {
        int y = (blk << 5) + k;
        float yf = (float)y - 127.5f;
        float A = fmaf(-s, yf, fmaf(-c, 127.5f, 127.5f));
        float B = fmaf( c, yf, fmaf(-s, 127.5f, 127.5f));
        float xa = (-1.f  - B) * inv_s;
        float xb = (256.f - B) * inv_s;
        float e0 = (-2.f  - A) * inv_c;
        float e1 = (258.f - A) * inv_c;
        float lo = fmaxf(xa, fminf(e0, e1));
        float hi = fminf(xb, fmaxf(e0, e1));
        int xlo = max(0,   (int)floorf(lo) - 2);
        int xhi = min(256, (int)ceilf(hi) + 3);
        if (xhi < xlo) xhi = xlo;
        // iy = 128.0 crossing: ownership boundary (floor(iy) 127 vs 128)
        float t128f = (128.f - B) * inv_s;
        // clamp to sane int range before cast
        t128f = fminf(fmaxf(t128f, -100000.f), 100000.f);
        int t128 = (int)floorf(t128f);
        int xbeg, xend;
        if (p == 0) { xbeg = xlo;                    xend = min(xhi, t128 + 3); }
        else        { xbeg = max(xlo, t128 - 2);     xend = xhi; }
        if (xbeg < xend) { mn = min(mn, xbeg); mx = max(mx, xend); }
    }
    if (mn >= mx) { mn = 0; mx = 0; }
    g_xrng[t] = make_int2(mn, mx);
}

extern __shared__ uint tile[];   // half2 per element

__global__ void __launch_bounds__(1024, 1)
fp_main_kernel(const float* __restrict__ vol, float* __restrict__ out)
{
    const int bx  = blockIdx.x;
    const int zp  = bx >> 3;          // z-pair 0..127
    const int p   = (bx >> 2) & 1;    // row-half phase
    const int vg  = bx & 3;           // view group of 4
    const int tid = threadIdx.x;

    __shared__ float s_c[16], s_s[16], s_Ac[16], s_Bc[16];
    if (tid < 16) {
        float unit = (float)(M_PI / 16.0);
        float mu   = (float)(M_PI / 180.0);
        float a = __fadd_rn(mu, __fmul_rn((float)tid, unit));
        double da = (double)a;
        float c = (float)cos(da), s = (float)sin(da);
        s_c[tid] = c; s_s[tid] = s;
        s_Ac[tid] = fmaf(-c, 127.5f, 127.5f);
        s_Bc[tid] = fmaf(-s, 127.5f, 127.5f);
    }

    // zero whole tile, then overlay data rows
    for (int i = tid; i < TROWS * TS; i += 1024) tile[i] = 0u;
    __syncthreads();

    const int r0     = p ? 128 : 0;   // first vol row in tile
    const int rowoff = p ? 5   : 2;   // its tile row
    const int nrows  = p ? 128 : 129;
    const float* __restrict__ v0 = vol + ((size_t)(zp << 1) << 16) + (r0 << 8);
    const float* __restrict__ v1 = v0 + 65536;
    for (int i = tid; i < nrows * 64; i += 1024) {
        int r = i >> 6, c4 = (i & 63) << 2;
        int off = (r << 8) + c4;
        float4 a = *(const float4*)(v0 + off);
        float4 b = *(const float4*)(v1 + off);
        uint* d = &tile[(r + rowoff) * TS + 2 + c4];
        uint t;
        PACKH(t, a.x, b.x); d[0] = t;
        PACKH(t, a.y, b.y); d[1] = t;
        PACKH(t, a.z, b.z); d[2] = t;
        PACKH(t, a.w, b.w); d[3] = t;
    }
    __syncthreads();

    const int warp = tid >> 5, lane = tid & 31;
    const int v    = (vg << 2) + (warp >> 3);   // this warp's view
    const int yblk = warp & 7;
    const int y    = (yblk << 5) + lane;        // this lane's output line

    // bit-domain clamps: tcol in [0,259], trow in [0,133]
    const int      LO_MIN = 0x4B400000 - 2,               LO_MAX = LO_MIN + 259;
    const int      HI_MIN = 0x4B400000 + (p ? 123 : -2),  HI_MAX = HI_MIN + 133;
    const unsigned UOFF   = (unsigned)HI_MIN * (unsigned)TS + (unsigned)LO_MIN;
    // seam kill: p0 valid trow 0..129 (floor(iy) <= 127);
    //            p1 valid trow 5..133 (floor(iy) >= 128)
    const int      KB = HI_MIN + (p ? 5 : 0);
    const unsigned KS = p ? 128u : 129u;

    const ull MAGIC2  = 0x4B4000004B400000ULL;
    const ull NMAGIC2 = 0xCB400000CB400000ULL;
    const ull HALF2C  = 0x3F0000003F000000ULL;
    const ull NONE2   = 0xBF800000BF800000ULL;
    const ull STEP1   = 0x3F8000003F800000ULL;  // (1, 1)

    const float c = s_c[v], s = s_s[v];
    const float yf = (float)y - 127.5f;
    const float A = fmaf(-s, yf, s_Ac[v]) - 0.5f;   // ix-0.5 = c*x + A
    const float B = fmaf( c, yf, s_Bc[v]) - 0.5f;   // iy-0.5 = s*x + B
    ull cs2, ab2;
    PK2(cs2, c, s);
    PK2(ab2, A, B);

    int2 rng = __ldg(&g_xrng[(p << 7) + (v << 3) + yblk]);
    const int xmin = rng.x, xmax = rng.y;
    if (xmin >= xmax) return;

    ull xf2, acc = 0ULL;
    const float xm = (float)xmin;
    PK2(xf2, xm, xm);

    #pragma unroll 2
    for (int x = xmin; x < xmax; x++) {
        ull ih2, m2, f2, wh2, w2;
        FMA2(ih2, cs2, xf2, ab2);      // (ix-.5, iy-.5)
        ADD2(m2,  ih2, MAGIC2);
        ADD2(f2,  m2,  NMAGIC2);       // (floor ix, floor iy)
        FMA2(wh2, f2,  NONE2, ih2);
        ADD2(w2,  wh2, HALF2C);        // (wx, wy)
        int blo = (int)(unsigned)m2;
        int bhi = (int)(unsigned)(m2 >> 32);
        bool ok = ((unsigned)(bhi - KB) <= KS);    // seam kill (pre-clamp trow)
        blo = min(max(blo, LO_MIN), LO_MAX);
        bhi = min(max(bhi, HI_MIN), HI_MAX);
        unsigned idx = (unsigned)bhi * (unsigned)TS + (unsigned)blo - UOFF;
        const uint* tp = &tile[idx];
        uint V00 = tp[0], V01 = tp[1], V10 = tp[TS], V11 = tp[TS + 1];
        float wx = __uint_as_float((unsigned)w2);
        float wy = __uint_as_float((unsigned)(w2 >> 32));
        uint WX, WY; BCASTH(WX, wx); BCASTH(WY, wy);
        uint D0, D1, H0, H1, DH, VAL;
        HSUB2(D0, V01, V00);
        HSUB2(D1, V11, V10);
        HFMA2(H0, WX, D0, V00);
        HFMA2(H1, WX, D1, V10);
        HSUB2(DH, H1, H0);
        HFMA2(VAL, WY, DH, H0);
        VAL = ok ? VAL : 0u;
        ull pv; H2P2(pv, VAL);
        ADD2(acc, acc, pv);
        ADD2(xf2, xf2, STEP1);
    }

    float a0, a1;
    UNPK2(a0, a1, acc);
    int oidx = ((((zp << 1) << 8) + y) << 4) + v;
    atomicAdd(&out[oidx],        a0);
    atomicAdd(&out[oidx + 4096], a1);
}

extern "C" void kernel_launch(void* const* d_in, const int* in_sizes, int n_in,
                              void* d_out, int out_size) {
    (void)in_sizes; (void)n_in;
    cudaFuncSetAttribute(fp_main_kernel,
                         cudaFuncAttributeMaxDynamicSharedMemorySize, TILE_BYTES);
    fp_zero_kernel<<<512, 512>>>((float4*)d_out, out_size / 4);
    fp_range_kernel<<<1, 256>>>();
    fp_main_kernel<<<1024, 1024, TILE_BYTES>>>((const float*)d_in[0], (float*)d_out);
}